// round 11
// baseline (speedup 1.0000x reference)
#include <cuda_runtime.h>
#include <cstdint>

// SoftNormalShader: gather vertex normals + barycentric interp + softmax RGB blend.
// N=4,H=512,W=512,K=8 ; V=50000, F=100000.
// Inputs (JAX x64 disabled => int arrays are int32):
//   0: verts_normals (V,3) f32   1: bary (P,8,3) f32   2: dists (P,8) f32
//   3: zbuf (P,8) f32            4: faces (F,3) i32    5: pix_to_face (P,8) i32
// Output: (N,H,W,4) float32
//
// R11: 2 px/thread, but pixel-1 raw data is staged through SMEM via cp.async
// (gmem->smem, no register landing) so the register peak is one pixel's worth
// (~40 regs) -> 6 blocks/SM (75% occ) while keeping 12x16B MLP at entry.
// Compacted while(mask) gather loop with register select-trees (no dynamic
// array indexing => no local memory). Per-face normal table (L2-resident);
// lazy bary with b2 reconstructed; ~1.06 of 8 samples pass (GAMMA underflow).

#define KSAMP 8
#define SIGMA_INV  1e4f
#define GAMMA_INV  1e4f
#define ZFAR_F     100.0f
#define INV_RANGE  (1.0f / 99.0f)
#define EPS_F      1e-10f

#define MAXF 131072

__device__ float4 g_fn[MAXF][3];   // per-face packed vertex normals

__global__ __launch_bounds__(256)
void prep_face_normals_kernel(const float* __restrict__ vn,
                              const int*   __restrict__ faces, int F)
{
    int idx = blockIdx.x * blockDim.x + threadIdx.x;   // (face, vert) pairs
    int f = idx / 3;
    int j = idx - f * 3;
    if (f >= F || f >= MAXF) return;
    int v = __ldg(faces + (long long)f * 3 + j);
    const float* n = vn + (long long)v * 3;
    g_fn[f][j] = make_float4(__ldg(n + 0), __ldg(n + 1), __ldg(n + 2), 0.0f);
}

// cp.async 16B: gmem -> smem without landing in registers (LDGSTS)
__device__ __forceinline__ void cp_async16(void* smem_dst, const void* gsrc) {
    unsigned s = (unsigned)__cvta_generic_to_shared(smem_dst);
    asm volatile("cp.async.cg.shared.global [%0], [%1], 16;" :: "r"(s), "l"(gsrc) : "memory");
}
#define CP_COMMIT() asm volatile("cp.async.commit_group;" ::: "memory")
#define CP_WAIT0()  asm volatile("cp.async.wait_group 0;" ::: "memory")

// 7-select binary trees: dynamic k -> register value, no local memory.
__device__ __forceinline__ float sel8f(const float* v, int k) {
    float x01 = (k & 1) ? v[1] : v[0];
    float x23 = (k & 1) ? v[3] : v[2];
    float x45 = (k & 1) ? v[5] : v[4];
    float x67 = (k & 1) ? v[7] : v[6];
    float y0  = (k & 2) ? x23 : x01;
    float y1  = (k & 2) ? x67 : x45;
    return (k & 4) ? y1 : y0;
}
__device__ __forceinline__ int sel8i(const int* v, int k) {
    int x01 = (k & 1) ? v[1] : v[0];
    int x23 = (k & 1) ? v[3] : v[2];
    int x45 = (k & 1) ? v[5] : v[4];
    int x67 = (k & 1) ? v[7] : v[6];
    int y0  = (k & 2) ? x23 : x01;
    int y1  = (k & 2) ? x67 : x45;
    return (k & 4) ? y1 : y0;
}

__device__ __forceinline__ void shade_pixel(
    float4 dv0, float4 dv1, float4 zv0, float4 zv1, int4 qv0, int4 qv1,
    const float* __restrict__ bary, float4* __restrict__ out, int pix)
{
    const long long base = (long long)pix * KSAMP;

    // statically-indexed register views
    float df[KSAMP] = { dv0.x, dv0.y, dv0.z, dv0.w, dv1.x, dv1.y, dv1.z, dv1.w };
    float zf[KSAMP] = { zv0.x, zv0.y, zv0.z, zv0.w, zv1.x, zv1.y, zv1.z, zv1.w };
    int   pf[KSAMP] = { qv0.x, qv0.y, qv0.z, qv0.w, qv1.x, qv1.y, qv1.z, qv1.w };

    // ---- pass 1: alpha product + zmax (scalars only; no pm/ze arrays) ----
    float zmax = 0.0f;                 // z_inv >= 0 (masked entries are 0)
    float one_minus_prod = 1.0f;
    #pragma unroll
    for (int k = 0; k < KSAMP; k++) {
        bool valid = pf[k] >= 0;
        float p = valid ? (1.0f / (1.0f + __expf(df[k] * SIGMA_INV))) : 0.0f;
        one_minus_prod *= (1.0f - p);
        float z = valid ? (ZFAR_F - zf[k]) * INV_RANGE : 0.0f;
        zmax = fmaxf(zmax, z);
    }

    // ---- candidate mask: exp((z-zmax)*1e4) flushes to 0 below ~-88 ----
    unsigned mask = 0;
    #pragma unroll
    for (int k = 0; k < KSAMP; k++) {
        float z = (ZFAR_F - zf[k]) * INV_RANGE;
        if (pf[k] >= 0 && (z - zmax) * GAMMA_INV > -88.0f)
            mask |= (1u << k);
    }

    // ---- compacted weight + gather loop (~1.06 iterations, lanes share) ----
    float wsum = 0.0f;
    float accr = 0.0f, accg = 0.0f, accb = 0.0f;
    while (mask) {
        int k = __ffs(mask) - 1;
        mask &= mask - 1;
        // register select trees — no local memory
        float d = sel8f(df, k);
        float zraw = sel8f(zf, k);
        int   f = sel8i(pf, k);
        float z = (ZFAR_F - zraw) * INV_RANGE;
        float p = 1.0f / (1.0f + __expf(d * SIGMA_INV));
        float w = p * __expf((z - zmax) * GAMMA_INV);
        wsum += w;
        // lazy bary: b0,b1 loaded; b2 reconstructed (sum == 1)
        const float* bp = bary + (base + k) * 3;
        float b0 = __ldg(bp + 0);
        float b1 = __ldg(bp + 1);
        float b2 = 1.0f - b0 - b1;
        // single-hop gather: per-face packed normals (L2-resident)
        const float4* fn = g_fn[f];
        float4 n0 = __ldg(fn + 0);
        float4 n1 = __ldg(fn + 1);
        float4 n2 = __ldg(fn + 2);
        accr += w * (b0 * n0.x + b1 * n1.x + b2 * n2.x);
        accg += w * (b0 * n0.y + b1 * n1.y + b2 * n2.y);
        accb += w * (b0 * n0.z + b1 * n1.z + b2 * n2.z);
    }

    // ---- blend ----
    float delta = fmaxf(__expf((EPS_F - zmax) * GAMMA_INV), EPS_F);
    float inv_denom = 1.0f / (wsum + delta);
    float4 o;
    o.x = (accr + delta) * inv_denom;   // background = (1,1,1)
    o.y = (accg + delta) * inv_denom;
    o.z = (accb + delta) * inv_denom;
    o.w = 1.0f - one_minus_prod;        // 1 - alpha
    __stcs(out + pix, o);
}

__global__ __launch_bounds__(256, 6)
void soft_normal_shader_kernel(
    const float* __restrict__ bary,    // (P,8,3)
    const float* __restrict__ dists,   // (P,8)
    const float* __restrict__ zbuf,    // (P,8)
    const int*   __restrict__ p2f,     // (P,8)
    float4*      __restrict__ out,     // (P,) rgba
    int npix)
{
    // SoA staging: stage[j][tx] -> consecutive float4 across lanes (conflict-free)
    __shared__ float4 stage[6][256];

    int tx  = threadIdx.x;
    int tid = blockIdx.x * blockDim.x + tx;
    int nthreads = gridDim.x * blockDim.x;

    // ---- pixel 1: cp.async gmem->smem (no register landing) ----
    int pix1 = tid + nthreads;
    {
        int p = (pix1 < npix) ? pix1 : (npix - 1);
        const long long b1 = (long long)p * KSAMP;
        cp_async16(&stage[0][tx], dists + b1);
        cp_async16(&stage[1][tx], dists + b1 + 4);
        cp_async16(&stage[2][tx], zbuf  + b1);
        cp_async16(&stage[3][tx], zbuf  + b1 + 4);
        cp_async16(&stage[4][tx], p2f   + b1);
        cp_async16(&stage[5][tx], p2f   + b1 + 4);
        CP_COMMIT();
    }

    // ---- pixel 0: register loads + full processing ----
    int pix0 = tid;
    if (pix0 < npix) {
        const long long b0 = (long long)pix0 * KSAMP;
        const float4* dp = reinterpret_cast<const float4*>(dists + b0);
        const float4* zp = reinterpret_cast<const float4*>(zbuf  + b0);
        const int4*   pp = reinterpret_cast<const int4*>(p2f + b0);
        float4 d0 = __ldcs(dp + 0), d1 = __ldcs(dp + 1);
        float4 z0 = __ldcs(zp + 0), z1 = __ldcs(zp + 1);
        int4   q0 = __ldcs(pp + 0), q1 = __ldcs(pp + 1);
        shade_pixel(d0, d1, z0, z1, q0, q1, bary, out, pix0);
    }

    // ---- pixel 1: from SMEM ----
    CP_WAIT0();
    if (pix1 < npix) {
        float4 d0 = stage[0][tx], d1 = stage[1][tx];
        float4 z0 = stage[2][tx], z1 = stage[3][tx];
        float4 qf0 = stage[4][tx], qf1 = stage[5][tx];
        int4 q0 = make_int4(__float_as_int(qf0.x), __float_as_int(qf0.y),
                            __float_as_int(qf0.z), __float_as_int(qf0.w));
        int4 q1 = make_int4(__float_as_int(qf1.x), __float_as_int(qf1.y),
                            __float_as_int(qf1.z), __float_as_int(qf1.w));
        shade_pixel(d0, d1, z0, z1, q0, q1, bary, out, pix1);
    }
}

extern "C" void kernel_launch(void* const* d_in, const int* in_sizes, int n_in,
                              void* d_out, int out_size)
{
    const float* vn    = (const float*)d_in[0];
    const float* bary  = (const float*)d_in[1];
    const float* dists = (const float*)d_in[2];
    const float* zbuf  = (const float*)d_in[3];
    const int*   faces = (const int*)d_in[4];
    const int*   p2f   = (const int*)d_in[5];
    float4*      out   = (float4*)d_out;

    int F = in_sizes[4] / 3;
    int npix = in_sizes[2] / KSAMP;   // N*H*W

    prep_face_normals_kernel<<<(3 * F + 255) / 256, 256>>>(vn, faces, F);

    int threads = 256;
    int total_threads = (npix + 1) / 2;
    int blocks = (total_threads + threads - 1) / threads;
    soft_normal_shader_kernel<<<blocks, threads>>>(bary, dists, zbuf, p2f, out, npix);
}

// round 12
// speedup vs baseline: 1.0274x; 1.0274x over previous
#include <cuda_runtime.h>
#include <cstdint>

// SoftNormalShader: gather vertex normals + barycentric interp + softmax RGB blend.
// N=4,H=512,W=512,K=8 ; V=50000, F=100000.
// Inputs (JAX x64 disabled => int arrays are int32):
//   0: verts_normals (V,3) f32   1: bary (P,8,3) f32   2: dists (P,8) f32
//   3: zbuf (P,8) f32            4: faces (F,3) i32    5: pix_to_face (P,8) i32
// Output: (N,H,W,4) float32
//
// R12: persistent grid-stride kernel with per-thread DOUBLE-BUFFERED cp.async
// staging of all streaming data (dists/zbuf/p2f) into SMEM. While processing
// tile t from buf A, tile t+1 is in flight into buf B -> in-flight streaming
// bytes are SMEM-capacity bound (~98KB/SM), not register-file bound. No
// barriers (thread-private slots; cp.async wait_group is per-thread state).
// Dynamic-k accesses become scalar LDS (no select trees / local memory).
// Gather (per-face normal table, L2-resident) issues from z+p2f only; the
// d-dependent sigmoid/alpha math fills the gather latency.

#define KSAMP 8
#define TPB   256
#define SIGMA_INV  1e4f
#define GAMMA_INV  1e4f
#define ZFAR_F     100.0f
#define INV_RANGE  (1.0f / 99.0f)
#define EPS_F      1e-10f

#define MAXF 131072

__device__ float4 g_fn[MAXF][3];   // per-face packed vertex normals

__global__ __launch_bounds__(256)
void prep_face_normals_kernel(const float* __restrict__ vn,
                              const int*   __restrict__ faces, int F)
{
    int idx = blockIdx.x * blockDim.x + threadIdx.x;   // (face, vert) pairs
    int f = idx / 3;
    int j = idx - f * 3;
    if (f >= F || f >= MAXF) return;
    int v = __ldg(faces + (long long)f * 3 + j);
    const float* n = vn + (long long)v * 3;
    g_fn[f][j] = make_float4(__ldg(n + 0), __ldg(n + 1), __ldg(n + 2), 0.0f);
}

// cp.async 16B: gmem -> smem without landing in registers (LDGSTS), L1-bypass
__device__ __forceinline__ void cp_async16(void* smem_dst, const void* gsrc) {
    unsigned s = (unsigned)__cvta_generic_to_shared(smem_dst);
    asm volatile("cp.async.cg.shared.global [%0], [%1], 16;" :: "r"(s), "l"(gsrc) : "memory");
}
#define CP_COMMIT() asm volatile("cp.async.commit_group;" ::: "memory")
#define CP_WAIT1()  asm volatile("cp.async.wait_group 1;" ::: "memory")

__global__ __launch_bounds__(TPB, 4)
void soft_normal_shader_kernel(
    const float* __restrict__ bary,    // (P,8,3)
    const float* __restrict__ dists,   // (P,8)
    const float* __restrict__ zbuf,    // (P,8)
    const int*   __restrict__ p2f,     // (P,8)
    float4*      __restrict__ out,     // (P,) rgba
    int npix)
{
    // thread-private staging slots; [buf][chunk][thread] float4 => lane stride
    // 16B => conflict-free LDS.128; 48KB total => 4 blocks/SM.
    __shared__ float4 sD[2][2][TPB];
    __shared__ float4 sZ[2][2][TPB];
    __shared__ int4   sP[2][2][TPB];

    const int tx = threadIdx.x;
    int pix = blockIdx.x * TPB + tx;
    const int stride = gridDim.x * TPB;

    // scalar views for dynamic-k access (smem dynamic indexing is free)
    const float* sDs = reinterpret_cast<const float*>(sD);
    const float* sZs = reinterpret_cast<const float*>(sZ);
    const int*   sPs = reinterpret_cast<const int*>(sP);

    // ---- prologue: stage first tile ----
    if (pix < npix) {
        const long long g = (long long)pix * KSAMP;
        cp_async16(&sD[0][0][tx], dists + g);
        cp_async16(&sD[0][1][tx], dists + g + 4);
        cp_async16(&sZ[0][0][tx], zbuf  + g);
        cp_async16(&sZ[0][1][tx], zbuf  + g + 4);
        cp_async16(&sP[0][0][tx], p2f   + g);
        cp_async16(&sP[0][1][tx], p2f   + g + 4);
    }
    CP_COMMIT();

    int buf = 0;
    while (pix < npix) {
        // ---- prefetch next tile into the other buffer ----
        int nxt = pix + stride;
        if (nxt < npix) {
            const long long g = (long long)nxt * KSAMP;
            cp_async16(&sD[buf^1][0][tx], dists + g);
            cp_async16(&sD[buf^1][1][tx], dists + g + 4);
            cp_async16(&sZ[buf^1][0][tx], zbuf  + g);
            cp_async16(&sZ[buf^1][1][tx], zbuf  + g + 4);
            cp_async16(&sP[buf^1][0][tx], p2f   + g);
            cp_async16(&sP[buf^1][1][tx], p2f   + g + 4);
        }
        CP_COMMIT();
        CP_WAIT1();            // current buffer's group complete; next stays in flight

        const long long base = (long long)pix * KSAMP;

        // ---- pass 1a: zmax + candidate mask (needs only z, p2f) ----
        float4 z0 = sZ[buf][0][tx], z1 = sZ[buf][1][tx];
        int4   q0 = sP[buf][0][tx], q1 = sP[buf][1][tx];
        float zf[KSAMP] = { z0.x, z0.y, z0.z, z0.w, z1.x, z1.y, z1.z, z1.w };
        int   pf[KSAMP] = { q0.x, q0.y, q0.z, q0.w, q1.x, q1.y, q1.z, q1.w };

        float zmax = 0.0f;                 // z_inv >= 0 (masked entries are 0)
        #pragma unroll
        for (int k = 0; k < KSAMP; k++) {
            float z = (pf[k] >= 0) ? (ZFAR_F - zf[k]) * INV_RANGE : 0.0f;
            zmax = fmaxf(zmax, z);
        }
        unsigned mask = 0;
        #pragma unroll
        for (int k = 0; k < KSAMP; k++) {
            float z = (ZFAR_F - zf[k]) * INV_RANGE;
            if (pf[k] >= 0 && (z - zmax) * GAMMA_INV > -88.0f)
                mask |= (1u << k);
        }

        // ---- pass 2: compacted gather loop (~1.06 iters; dynamic k via LDS) ----
        float wsum = 0.0f;
        float accr = 0.0f, accg = 0.0f, accb = 0.0f;
        while (mask) {
            int k = __ffs(mask) - 1;
            mask &= mask - 1;
            int sidx = ((buf * 2 + (k >> 2)) * TPB + tx) * 4 + (k & 3);
            int   f = sPs[sidx];
            // issue gathers first (from f alone) so they fly during the math
            const float4* fn = g_fn[f];
            float4 n0 = __ldg(fn + 0);
            float4 n1 = __ldg(fn + 1);
            float4 n2 = __ldg(fn + 2);
            const float* bp = bary + (base + k) * 3;
            float b0 = __ldcs(bp + 0);
            float b1 = __ldcs(bp + 1);
            float d  = sDs[sidx];
            float zr = sZs[sidx];
            float z  = (ZFAR_F - zr) * INV_RANGE;
            float p  = 1.0f / (1.0f + __expf(d * SIGMA_INV));
            float w  = p * __expf((z - zmax) * GAMMA_INV);
            wsum += w;
            float b2 = 1.0f - b0 - b1;   // barycentrics sum to 1
            accr += w * (b0 * n0.x + b1 * n1.x + b2 * n2.x);
            accg += w * (b0 * n0.y + b1 * n1.y + b2 * n2.y);
            accb += w * (b0 * n0.z + b1 * n1.z + b2 * n2.z);
        }

        // ---- pass 1b: alpha product (d-dependent; overlaps gather latency) ----
        float4 d0 = sD[buf][0][tx], d1 = sD[buf][1][tx];
        float df[KSAMP] = { d0.x, d0.y, d0.z, d0.w, d1.x, d1.y, d1.z, d1.w };
        float one_minus_prod = 1.0f;
        #pragma unroll
        for (int k = 0; k < KSAMP; k++) {
            float p = (pf[k] >= 0) ? (1.0f / (1.0f + __expf(df[k] * SIGMA_INV))) : 0.0f;
            one_minus_prod *= (1.0f - p);
        }

        // ---- blend + store ----
        float delta = fmaxf(__expf((EPS_F - zmax) * GAMMA_INV), EPS_F);
        float inv_denom = 1.0f / (wsum + delta);
        float4 o;
        o.x = (accr + delta) * inv_denom;   // background = (1,1,1)
        o.y = (accg + delta) * inv_denom;
        o.z = (accb + delta) * inv_denom;
        o.w = 1.0f - one_minus_prod;        // 1 - alpha
        __stcs(out + pix, o);

        pix = nxt;
        buf ^= 1;
    }
}

extern "C" void kernel_launch(void* const* d_in, const int* in_sizes, int n_in,
                              void* d_out, int out_size)
{
    const float* vn    = (const float*)d_in[0];
    const float* bary  = (const float*)d_in[1];
    const float* dists = (const float*)d_in[2];
    const float* zbuf  = (const float*)d_in[3];
    const int*   faces = (const int*)d_in[4];
    const int*   p2f   = (const int*)d_in[5];
    float4*      out   = (float4*)d_out;

    int F = in_sizes[4] / 3;
    int npix = in_sizes[2] / KSAMP;   // N*H*W

    prep_face_normals_kernel<<<(3 * F + 255) / 256, 256>>>(vn, faces, F);

    // persistent: 4 blocks/SM x 148 SMs (smem-bound occupancy)
    int blocks = 592;
    soft_normal_shader_kernel<<<blocks, TPB>>>(bary, dists, zbuf, p2f, out, npix);
}